// round 16
// baseline (speedup 1.0000x reference)
#include <cuda_runtime.h>
#include <cuda_fp16.h>
#include <cstdint>

#define BATCH 4
#define SEQ   2048
#define DMODEL 1024
#define NBT   (SEQ / 128)     // 16 bn tiles per scores row-block

// Scratch (device globals — no cudaMalloc allowed)
__device__ __half g_QKV16[(size_t)3 * BATCH * SEQ * DMODEL];  // 48 MB (Q,K planes used)
__device__ __half g_P16 [(size_t)BATCH * SEQ * SEQ];          // 32 MB (unnormalized exp-scores)
__device__ __half g_AO16[(size_t)BATCH * SEQ * DMODEL];       // 16 MB
__device__ __half g_X16 [(size_t)BATCH * SEQ * DMODEL];       // 16 MB (fp16 x)
__device__ __half g_W16 [(size_t)4 * DMODEL * DMODEL];        // 8 MB (WqT,WkT,WvT,WoT)
__device__ __half g_VT16[(size_t)BATCH * SEQ * DMODEL];       // 16 MB (V^T per batch)
__device__ float  g_PS  [(size_t)NBT * BATCH * SEQ];          // 512 KB (row partial sums)
__device__ float  g_RS  [(size_t)BATCH * SEQ];                // 32 KB (1/rowsum)

__device__ __forceinline__ void mma16(float c[4], const uint32_t a[4], const uint32_t b[2]) {
    asm volatile(
        "mma.sync.aligned.m16n8k16.row.col.f32.f16.f16.f32 "
        "{%0,%1,%2,%3}, {%4,%5,%6,%7}, {%8,%9}, {%0,%1,%2,%3};\n"
        : "+f"(c[0]), "+f"(c[1]), "+f"(c[2]), "+f"(c[3])
        : "r"(a[0]), "r"(a[1]), "r"(a[2]), "r"(a[3]), "r"(b[0]), "r"(b[1]));
}

__device__ __forceinline__ void cpa16s(uint32_t dst, const void* src) {
    asm volatile("cp.async.cg.shared.global [%0], [%1], 16;\n" :: "r"(dst), "l"(src));
}

__device__ __forceinline__ void ldmx4s(uint32_t r[4], uint32_t addr) {
    asm volatile("ldmatrix.sync.aligned.m8n8.x4.shared.b16 {%0,%1,%2,%3}, [%4];"
        : "=r"(r[0]), "=r"(r[1]), "=r"(r[2]), "=r"(r[3]) : "r"(addr));
}

// SW128-style XOR swizzle on byte offsets (16B granular)
__device__ __forceinline__ uint32_t sw128(uint32_t off) {
    return off ^ ((off >> 3) & 0x70u);
}

// ---------------- pre-pass kernels ----------------

// fp32 -> fp16 conversion (4 elems/thread)
__global__ void to_half(const float4* __restrict__ in, __half* __restrict__ out, int n4)
{
    int i = blockIdx.x * blockDim.x + threadIdx.x;
    if (i < n4) {
        float4 v = in[i];
        __half2* o = (__half2*)(out + (size_t)i * 4);
        o[0] = __floats2half2_rn(v.x, v.y);
        o[1] = __floats2half2_rn(v.z, v.w);
    }
}

// Fused 4-weight transpose + fp16 convert: z selects source W; out plane z.
__global__ void transpose_w_h(const float* __restrict__ W0, const float* __restrict__ W1,
                              const float* __restrict__ W2, const float* __restrict__ W3,
                              __half* __restrict__ out)
{
    __shared__ float tile[32][33];
    const int z = blockIdx.z;
    const float* in = (z == 0) ? W0 : (z == 1) ? W1 : (z == 2) ? W2 : W3;
    out += (size_t)z * DMODEL * DMODEL;
    const int bx = blockIdx.x * 32;
    const int by = blockIdx.y * 32;
    const int tx = threadIdx.x, ty = threadIdx.y;
    #pragma unroll
    for (int i = 0; i < 32; i += 8)
        tile[ty + i][tx] = in[(size_t)(by + ty + i) * DMODEL + bx + tx];
    __syncthreads();
    #pragma unroll
    for (int i = 0; i < 32; i += 8)
        out[(size_t)(bx + ty + i) * DMODEL + by + tx] = __float2half_rn(tile[tx][ty + i]);
}

// Final rowsum inversion: combine NBT partials per row.
__global__ void rowsum_inv16(const float* __restrict__ ps, float* __restrict__ inv)
{
    const int r = blockIdx.x * 256 + threadIdx.x;
    if (r < BATCH * SEQ) {
        float s = 0.f;
        #pragma unroll
        for (int i = 0; i < NBT; i++)
            s += ps[(size_t)i * (BATCH * SEQ) + r];
        inv[r] = 1.0f / s;
    }
}

// ---------------- NT FP16 GEMM: C[M,N] = A[M,K] * B[N,K]^T ----------------
// CTA tile 128x128x64, 4 warps (2x2), warp tile 64x64, 3-stage cp.async,
// XOR-swizzled smem, ldmatrix fragments (double-buffered), fp32 accumulate.
//   TRIPLE: blockIdx.z selects B among {B0,B1,B2}; z==2 writes transposed to vt (fp16).
//   HALF_OUT: store C as fp16 (else fp32).
//   MASKED: p = exp(v*scale) (masked -> 0), fp16 store; per-tile row partials -> psOut.
//   rowinv: multiply row r by rowinv[bz*M+r] before store (PV path).
template<bool TRIPLE, bool HALF_OUT, bool MASKED>
__global__ __launch_bounds__(128, 2)
void gemm_h(const __half* __restrict__ A, const __half* __restrict__ B0,
            const __half* __restrict__ B1, const __half* __restrict__ B2,
            void* __restrict__ Cv, int M, int N, int K,
            size_t sA, size_t sB, size_t sC,
            const unsigned char* __restrict__ mask, float scale,
            const float* __restrict__ rowinv, __half* __restrict__ vt,
            float* __restrict__ psOut)
{
    constexpr int BK = 64;                        // halves per K-tile (128 B rows)
    constexpr uint32_t TILE_B = 128u * 128u;      // 16 KB per operand tile
    constexpr uint32_t STG_B  = 2u * TILE_B;      // 32 KB per stage
    constexpr int NSTAGE = 3;

    extern __shared__ float smf[];
    __shared__ int mask_is_int32;

    const int bz = blockIdx.z;
    const __half* B;
    float*  C32 = (float*)Cv;
    __half* C16 = (__half*)Cv;
    if (TRIPLE) {
        B = (bz == 0) ? B0 : (bz == 1 ? B1 : B2);
        C16 += (size_t)bz * sC;
    } else {
        B = B0 + (size_t)bz * sB;
        A += (size_t)bz * sA;
        C32 += (size_t)bz * sC;
        C16 += (size_t)bz * sC;
    }

    const int bm = blockIdx.y * 128;
    const int bn = blockIdx.x * 128;
    const int t    = threadIdx.x;
    const int lane = t & 31;
    const int wid  = t >> 5;
    const int wm   = wid >> 1;        // 0..1 (M)
    const int wn   = wid & 1;         // 0..1 (N)
    const int g    = lane >> 2;       // 0..7
    const int tig  = lane & 3;        // 0..3

    uint32_t smem_base = (uint32_t)__cvta_generic_to_shared(smf);
    smem_base = (smem_base + 127u) & ~127u;

    if (MASKED && t == 0) {
        int is_int = 1;
        #pragma unroll 4
        for (int i = 0; i < 256; i++)
            if ((i & 3) != 0 && mask[i] != 0) is_int = 0;
        mask_is_int32 = is_int;
    }

    float acc[4][8][4];
    #pragma unroll
    for (int i = 0; i < 4; i++)
        #pragma unroll
        for (int j = 0; j < 8; j++)
            #pragma unroll
            for (int r = 0; r < 4; r++) acc[i][j][r] = 0.f;

    const int nkt = K / BK;

    auto issue = [&](int kt) {
        const uint32_t abase = smem_base + (uint32_t)(kt % NSTAGE) * STG_B;
        const uint32_t bbase = abase + TILE_B;
        const __half* gA = A + (size_t)bm * K + (size_t)kt * BK;
        const __half* gB = B + (size_t)bn * K + (size_t)kt * BK;
        #pragma unroll
        for (int i = 0; i < 8; i++) {
            const int chunk = t + i * 128;          // 0..1023
            const int row = chunk >> 3, kc = chunk & 7;
            const uint32_t sw = sw128((uint32_t)(row * 128 + kc * 16));
            cpa16s(abase + sw, gA + (size_t)row * K + kc * 8);
            cpa16s(bbase + sw, gB + (size_t)row * K + kc * 8);
        }
        asm volatile("cp.async.commit_group;\n");
    };

    issue(0); issue(1);

    // ldmatrix per-lane selectors (byte offsets)
    const int a_row  = (lane & 15);
    const int a_kofb = (lane >> 4) << 4;                  // 0 or 16 bytes
    const int b_row  = (lane & 7) + ((lane & 16) >> 1);
    const int b_kofb = (lane & 8) << 1;                   // 0 or 16 bytes

    uint32_t af[2][4][4];
    uint32_t bf[2][8][2];

    for (int kt = 0; kt < nkt; ++kt) {
        if (kt + 1 < nkt) asm volatile("cp.async.wait_group 1;\n");
        else              asm volatile("cp.async.wait_group 0;\n");
        __syncthreads();

        const uint32_t abase = smem_base + (uint32_t)(kt % NSTAGE) * STG_B;
        const uint32_t bbase = abase + TILE_B;

        auto ldfrag = [&](int ks, int buf) {     // ks: k16 step within k64 tile
            const uint32_t kb = (uint32_t)ks * 32;
            #pragma unroll
            for (int i = 0; i < 4; i++) {
                const int rb = wm * 64 + i * 16;
                const uint32_t off = (uint32_t)((rb + a_row) * 128) + kb + a_kofb;
                ldmx4s(af[buf][i], abase + sw128(off));
            }
            #pragma unroll
            for (int jp = 0; jp < 4; jp++) {
                uint32_t bq[4];
                const int nb = wn * 64 + jp * 16;
                const uint32_t off = (uint32_t)((nb + b_row) * 128) + kb + b_kofb;
                ldmx4s(bq, bbase + sw128(off));
                bf[buf][jp * 2][0]     = bq[0];
                bf[buf][jp * 2][1]     = bq[1];
                bf[buf][jp * 2 + 1][0] = bq[2];
                bf[buf][jp * 2 + 1][1] = bq[3];
            }
        };

        ldfrag(0, 0);
        if (kt + 2 < nkt) issue(kt + 2);

        #pragma unroll
        for (int ks = 0; ks < 4; ++ks) {
            const int cur = ks & 1;
            if (ks < 3) ldfrag(ks + 1, cur ^ 1);
            #pragma unroll
            for (int i = 0; i < 4; i++)
                #pragma unroll
                for (int j = 0; j < 8; j++)
                    mma16(acc[i][j], af[cur][i], bf[cur][j]);
        }
    }

    // ---- epilogue ----
    if (TRIPLE && bz == 2) {
        // V plane: write transposed fp16 (VT[b][d][s]) via smem staging; skip C store.
        __syncthreads();
        float* ts = smf;                 // [128][129] floats
        #pragma unroll
        for (int i = 0; i < 4; i++) {
            const int rl = wm * 64 + i * 16 + g;
            #pragma unroll
            for (int j = 0; j < 8; j++) {
                const int cl = wn * 64 + j * 8 + tig * 2;
                ts[rl * 129 + cl]           = acc[i][j][0];
                ts[rl * 129 + cl + 1]       = acc[i][j][1];
                ts[(rl + 8) * 129 + cl]     = acc[i][j][2];
                ts[(rl + 8) * 129 + cl + 1] = acc[i][j][3];
            }
        }
        __syncthreads();
        const int b     = bm >> 11;
        const int sbase = bm & 2047;
        __half* vtp = vt + (size_t)b * ((size_t)SEQ * DMODEL);
        #pragma unroll 4
        for (int i = 0; i < 32; i++) {
            const int c = wid * 32 + i;
            __half* dstrow = vtp + (size_t)(bn + c) * SEQ + sbase;
            #pragma unroll
            for (int ch = 0; ch < 4; ch++) {
                const int s = lane + ch * 32;
                dstrow[s] = __float2half_rn(ts[s * 129 + c]);
            }
        }
        return;
    }

    float rp[4][2];
    if (MASKED) {
        #pragma unroll
        for (int i = 0; i < 4; i++) { rp[i][0] = 0.f; rp[i][1] = 0.f; }
    }

    #pragma unroll
    for (int i = 0; i < 4; i++) {
        const int r0 = bm + wm * 64 + i * 16 + g;
        float ri0 = 1.f, ri1 = 1.f;
        if (!MASKED && rowinv) {
            ri0 = rowinv[(size_t)bz * M + r0];
            ri1 = rowinv[(size_t)bz * M + r0 + 8];
        }
        #pragma unroll
        for (int j = 0; j < 8; j++) {
            const int c0 = bn + wn * 64 + j * 8 + tig * 2;
            float v0 = acc[i][j][0], v1 = acc[i][j][1];
            float v2 = acc[i][j][2], v3 = acc[i][j][3];
            if (MASKED) {
                // scores path: p = exp(v*scale) (masked -> 0), fp16 store
                const size_t base = (size_t)bz * (size_t)M * N + (size_t)r0 * N;
                int m00, m01, m10, m11;
                if (mask_is_int32) {
                    const int* mi = (const int*)mask;
                    int2 ma = *(const int2*)&mi[base + c0];
                    int2 mb = *(const int2*)&mi[base + (size_t)8 * N + c0];
                    m00 = ma.x; m01 = ma.y; m10 = mb.x; m11 = mb.y;
                } else {
                    m00 = mask[base + c0];                   m01 = mask[base + c0 + 1];
                    m10 = mask[base + (size_t)8 * N + c0];   m11 = mask[base + (size_t)8 * N + c0 + 1];
                }
                v0 = m00 ? __expf(v0 * scale) : 0.f;
                v1 = m01 ? __expf(v1 * scale) : 0.f;
                v2 = m10 ? __expf(v2 * scale) : 0.f;
                v3 = m11 ? __expf(v3 * scale) : 0.f;
                rp[i][0] += v0 + v1;
                rp[i][1] += v2 + v3;
            } else if (rowinv) {
                v0 *= ri0; v1 *= ri0; v2 *= ri1; v3 *= ri1;
            }
            if (HALF_OUT) {
                *(__half2*)&C16[(size_t)r0 * N + c0]       = __floats2half2_rn(v0, v1);
                *(__half2*)&C16[(size_t)(r0 + 8) * N + c0] = __floats2half2_rn(v2, v3);
            } else {
                float2 w0 = {v0, v1}, w1 = {v2, v3};
                *(float2*)&C32[(size_t)r0 * N + c0]       = w0;
                *(float2*)&C32[(size_t)(r0 + 8) * N + c0] = w1;
            }
        }
    }

    if (MASKED) {
        // Reduce partial row sums: tig lanes -> per-warp; smem combine across wn.
        float* ps = smf;                 // [2][128] floats (stage smem reusable)
        __syncthreads();                 // all warps done with stage smem reads
        #pragma unroll
        for (int i = 0; i < 4; i++) {
            #pragma unroll
            for (int h = 0; h < 2; h++) {
                float s = rp[i][h];
                s += __shfl_xor_sync(0xffffffffu, s, 1);
                s += __shfl_xor_sync(0xffffffffu, s, 2);
                if (tig == 0)
                    ps[wn * 128 + wm * 64 + i * 16 + h * 8 + g] = s;
            }
        }
        __syncthreads();
        if (t < 128) {
            const float total = ps[t] + ps[128 + t];
            psOut[(size_t)blockIdx.x * (BATCH * SEQ) + (size_t)bz * M + bm + t] = total;
        }
    }
}

// ---------------- host ----------------

extern "C" void kernel_launch(void* const* d_in, const int* in_sizes, int n_in,
                              void* d_out, int out_size)
{
    const float*         x    = (const float*)d_in[0];
    const unsigned char* mask = (const unsigned char*)d_in[1];
    const float*         Wq   = (const float*)d_in[2];
    const float*         Wk   = (const float*)d_in[3];
    const float*         Wv   = (const float*)d_in[4];
    const float*         Wo   = (const float*)d_in[5];
    float*               out  = (float*)d_out;

    __half *QKV, *P16, *AO, *X, *W, *VT;
    float *RS, *PS;
    cudaGetSymbolAddress((void**)&QKV, g_QKV16);
    cudaGetSymbolAddress((void**)&P16, g_P16);
    cudaGetSymbolAddress((void**)&AO,  g_AO16);
    cudaGetSymbolAddress((void**)&X,   g_X16);
    cudaGetSymbolAddress((void**)&W,   g_W16);
    cudaGetSymbolAddress((void**)&VT,  g_VT16);
    cudaGetSymbolAddress((void**)&RS,  g_RS);
    cudaGetSymbolAddress((void**)&PS,  g_PS);

    const size_t pstride = (size_t)BATCH * SEQ * DMODEL;   // full Q/K/V plane (elems)
    const size_t bstride = (size_t)SEQ * DMODEL;           // per-batch plane
    const size_t wsz = (size_t)DMODEL * DMODEL;
    __half* WqT = W;
    __half* WkT = W + wsz;
    __half* WvT = W + 2 * wsz;
    __half* WoT = W + 3 * wsz;
    __half* Q  = QKV;
    __half* Kp = QKV + pstride;

    // --- pre-pass: x -> fp16; fused transpose+fp16 of all weights ---
    {
        const int xe4 = (int)(pstride / 4);
        to_half<<<(xe4 + 255) / 256, 256>>>((const float4*)x, X, xe4);
        dim3 tb(32, 8);
        dim3 tgw(DMODEL / 32, DMODEL / 32, 4);
        transpose_w_h<<<tgw, tb>>>(Wq, Wk, Wv, Wo, W);
    }

    const int smemB = 3 * 32768 + 128;   // 3 stages + alignment slack
    cudaFuncSetAttribute(gemm_h<true,  true,  false>,
                         cudaFuncAttributeMaxDynamicSharedMemorySize, smemB);
    cudaFuncSetAttribute(gemm_h<false, true,  true>,
                         cudaFuncAttributeMaxDynamicSharedMemorySize, smemB);
    cudaFuncSetAttribute(gemm_h<false, true,  false>,
                         cudaFuncAttributeMaxDynamicSharedMemorySize, smemB);
    cudaFuncSetAttribute(gemm_h<false, false, false>,
                         cudaFuncAttributeMaxDynamicSharedMemorySize, smemB);

    const int MS = BATCH * SEQ;   // 8192
    dim3 blk(128);

    // QKV projections fused: z in {Q,K,V}; V written transposed into VT (fp16)
    dim3 gq(DMODEL / 128, MS / 128, 3);
    gemm_h<true, true, false><<<gq, blk, smemB>>>(
        X, WqT, WkT, WvT, QKV, MS, DMODEL, DMODEL, 0, 0, pstride,
        nullptr, 1.f, nullptr, VT, nullptr);

    // P = exp(Q K^T / 32) masked->0, fp16 out; per-tile row partials -> PS
    dim3 gs(SEQ / 128, SEQ / 128, BATCH);
    gemm_h<false, true, true><<<gs, blk, smemB>>>(
        Q, Kp, nullptr, nullptr, P16, SEQ, SEQ, DMODEL,
        bstride, bstride, (size_t)SEQ * SEQ, mask, 0.03125f, nullptr, nullptr, PS);

    // 1/rowsum from partials
    rowsum_inv16<<<(BATCH * SEQ + 255) / 256, 256>>>(PS, RS);

    // attn_out = (P V) * rowinv  (fp16 out)
    dim3 gv(DMODEL / 128, SEQ / 128, BATCH);
    gemm_h<false, true, false><<<gv, blk, smemB>>>(
        P16, VT, nullptr, nullptr, AO, SEQ, DMODEL, SEQ,
        (size_t)SEQ * SEQ, bstride, bstride, nullptr, 1.f, RS, nullptr, nullptr);

    // output projection -> d_out (fp32)
    dim3 go(DMODEL / 128, MS / 128, 1);
    gemm_h<false, false, false><<<go, blk, smemB>>>(
        AO, WoT, nullptr, nullptr, out, MS, DMODEL, DMODEL, 0, 0, 0,
        nullptr, 1.f, nullptr, nullptr, nullptr);
}

// round 17
// speedup vs baseline: 1.2286x; 1.2286x over previous
#include <cuda_runtime.h>
#include <cuda_fp16.h>
#include <cstdint>

#define BATCH 4
#define SEQ   2048
#define DMODEL 1024

// Scratch (device globals — no cudaMalloc allowed)
__device__ __half g_X16 [(size_t)BATCH * SEQ * DMODEL];       // 16 MB (fp16 x)
__device__ __half g_T16 [(size_t)BATCH * SEQ * DMODEL];       // 16 MB (T = x*Wqk)
__device__ __half g_P16 [(size_t)BATCH * SEQ * SEQ];          // 32 MB (unnormalized exp-scores)
__device__ __half g_VT16[(size_t)BATCH * SEQ * DMODEL];       // 16 MB (VO^T per batch)
__device__ __half g_WH  [(size_t)6 * DMODEL * DMODEL];        // 12 MB: q16,k16,v16,WoT,WqkT,WvoT
__device__ float  g_RS  [(size_t)BATCH * SEQ];                // 32 KB (1/rowsum)

__device__ __forceinline__ void mma16(float c[4], const uint32_t a[4], const uint32_t b[2]) {
    asm volatile(
        "mma.sync.aligned.m16n8k16.row.col.f32.f16.f16.f32 "
        "{%0,%1,%2,%3}, {%4,%5,%6,%7}, {%8,%9}, {%0,%1,%2,%3};\n"
        : "+f"(c[0]), "+f"(c[1]), "+f"(c[2]), "+f"(c[3])
        : "r"(a[0]), "r"(a[1]), "r"(a[2]), "r"(a[3]), "r"(b[0]), "r"(b[1]));
}

__device__ __forceinline__ void cpa16s(uint32_t dst, const void* src) {
    asm volatile("cp.async.cg.shared.global [%0], [%1], 16;\n" :: "r"(dst), "l"(src));
}

__device__ __forceinline__ void ldmx4s(uint32_t r[4], uint32_t addr) {
    asm volatile("ldmatrix.sync.aligned.m8n8.x4.shared.b16 {%0,%1,%2,%3}, [%4];"
        : "=r"(r[0]), "=r"(r[1]), "=r"(r[2]), "=r"(r[3]) : "r"(addr));
}

// SW128-style XOR swizzle on byte offsets (16B granular)
__device__ __forceinline__ uint32_t sw128(uint32_t off) {
    return off ^ ((off >> 3) & 0x70u);
}

// ---------------- pre-pass kernels ----------------

// fp32 -> fp16 conversion (4 elems/thread)
__global__ void to_half(const float4* __restrict__ in, __half* __restrict__ out, int n4)
{
    int i = blockIdx.x * blockDim.x + threadIdx.x;
    if (i < n4) {
        float4 v = in[i];
        __half2* o = (__half2*)(out + (size_t)i * 4);
        o[0] = __floats2half2_rn(v.x, v.y);
        o[1] = __floats2half2_rn(v.z, v.w);
    }
}

// Transpose + fp16: out[n*D + e] = in[e*D + n]  (WoT from Wo)
__global__ void transpose_h(const float* __restrict__ in, __half* __restrict__ out)
{
    __shared__ float tile[32][33];
    const int bx = blockIdx.x * 32;
    const int by = blockIdx.y * 32;
    const int tx = threadIdx.x, ty = threadIdx.y;
    #pragma unroll
    for (int i = 0; i < 32; i += 8)
        tile[ty + i][tx] = in[(size_t)(by + ty + i) * DMODEL + bx + tx];
    __syncthreads();
    #pragma unroll
    for (int i = 0; i < 32; i += 8)
        out[(size_t)(bx + ty + i) * DMODEL + by + tx] = __float2half_rn(tile[tx][ty + i]);
}

// 1/rowsum over 2048-wide fp16 rows (deterministic tree reduction).
__global__ void rowsum_inv_h(const __half* __restrict__ P, float* __restrict__ inv)
{
    const __half* p = P + (size_t)blockIdx.x * 2048;
    const int t = threadIdx.x, lane = t & 31, wid = t >> 5;
    __shared__ float red[8];
    uint4 u = ((const uint4*)p)[t];          // 8 halves
    const __half2* h = (const __half2*)&u;
    float s = 0.f;
    #pragma unroll
    for (int i = 0; i < 4; i++) {
        float2 f = __half22float2(h[i]);
        s += f.x + f.y;
    }
    #pragma unroll
    for (int o = 16; o; o >>= 1) s += __shfl_xor_sync(0xffffffffu, s, o);
    if (lane == 0) red[wid] = s;
    __syncthreads();
    if (t == 0) {
        float bs = red[0];
        #pragma unroll
        for (int w = 1; w < 8; w++) bs += red[w];
        inv[blockIdx.x] = 1.0f / bs;
    }
}

// ---------------- NT FP16 GEMM: C[M,N] = A[M,K] * B[N,K]^T ----------------
// CTA tile 128x128x64, 4 warps (2x2), warp tile 64x64, 3-stage cp.async,
// XOR-swizzled smem, ldmatrix fragments (double-buffered), fp32 accumulate.
//   TRIPLE: bz selects A in {A0,A1} and B in {B0,B1}; C += bz*sC;
//           if vt!=null && bz==vtz: write result transposed to vt (fp16), skip C.
//   HALF_OUT: store C as fp16 (else fp32).
//   MASKED: p = exp(v*scale) (masked -> 0), fp16 store (scores path).
//   rowinv: multiply row r by rowinv[bz*M+r] before store (final path).
template<bool TRIPLE, bool HALF_OUT, bool MASKED>
__global__ __launch_bounds__(128, 2)
void gemm_h(const __half* __restrict__ A0, const __half* __restrict__ A1,
            const __half* __restrict__ B0, const __half* __restrict__ B1,
            void* __restrict__ Cv, int M, int N, int K,
            size_t sA, size_t sB, size_t sC,
            const unsigned char* __restrict__ mask, float scale,
            const float* __restrict__ rowinv, __half* __restrict__ vt, int vtz)
{
    constexpr int BK = 64;                        // halves per K-tile (128 B rows)
    constexpr uint32_t TILE_B = 128u * 128u;      // 16 KB per operand tile
    constexpr uint32_t STG_B  = 2u * TILE_B;      // 32 KB per stage
    constexpr int NSTAGE = 3;

    extern __shared__ float smf[];
    __shared__ int mask_is_int32;

    const int bz = blockIdx.z;
    const __half* A;
    const __half* B;
    float*  C32 = (float*)Cv;
    __half* C16 = (__half*)Cv;
    if (TRIPLE) {
        A = (bz == 0) ? A0 : A1;
        B = (bz == 0) ? B0 : B1;
        C16 += (size_t)bz * sC;
        C32 += (size_t)bz * sC;
    } else {
        A = A0 + (size_t)bz * sA;
        B = B0 + (size_t)bz * sB;
        C32 += (size_t)bz * sC;
        C16 += (size_t)bz * sC;
    }

    const int bm = blockIdx.y * 128;
    const int bn = blockIdx.x * 128;
    const int t    = threadIdx.x;
    const int lane = t & 31;
    const int wid  = t >> 5;
    const int wm   = wid >> 1;        // 0..1 (M)
    const int wn   = wid & 1;         // 0..1 (N)
    const int g    = lane >> 2;       // 0..7
    const int tig  = lane & 3;        // 0..3

    uint32_t smem_base = (uint32_t)__cvta_generic_to_shared(smf);
    smem_base = (smem_base + 127u) & ~127u;

    if (MASKED && t == 0) {
        int is_int = 1;
        #pragma unroll 4
        for (int i = 0; i < 256; i++)
            if ((i & 3) != 0 && mask[i] != 0) is_int = 0;
        mask_is_int32 = is_int;
    }

    float acc[4][8][4];
    #pragma unroll
    for (int i = 0; i < 4; i++)
        #pragma unroll
        for (int j = 0; j < 8; j++)
            #pragma unroll
            for (int r = 0; r < 4; r++) acc[i][j][r] = 0.f;

    const int nkt = K / BK;

    auto issue = [&](int kt) {
        const uint32_t abase = smem_base + (uint32_t)(kt % NSTAGE) * STG_B;
        const uint32_t bbase = abase + TILE_B;
        const __half* gA = A + (size_t)bm * K + (size_t)kt * BK;
        const __half* gB = B + (size_t)bn * K + (size_t)kt * BK;
        #pragma unroll
        for (int i = 0; i < 8; i++) {
            const int chunk = t + i * 128;          // 0..1023
            const int row = chunk >> 3, kc = chunk & 7;
            const uint32_t sw = sw128((uint32_t)(row * 128 + kc * 16));
            cpa16s(abase + sw, gA + (size_t)row * K + kc * 8);
            cpa16s(bbase + sw, gB + (size_t)row * K + kc * 8);
        }
        asm volatile("cp.async.commit_group;\n");
    };

    issue(0); issue(1);

    // ldmatrix per-lane selectors (byte offsets)
    const int a_row  = (lane & 15);
    const int a_kofb = (lane >> 4) << 4;                  // 0 or 16 bytes
    const int b_row  = (lane & 7) + ((lane & 16) >> 1);
    const int b_kofb = (lane & 8) << 1;                   // 0 or 16 bytes

    uint32_t af[2][4][4];
    uint32_t bf[2][8][2];

    for (int kt = 0; kt < nkt; ++kt) {
        if (kt + 1 < nkt) asm volatile("cp.async.wait_group 1;\n");
        else              asm volatile("cp.async.wait_group 0;\n");
        __syncthreads();

        const uint32_t abase = smem_base + (uint32_t)(kt % NSTAGE) * STG_B;
        const uint32_t bbase = abase + TILE_B;

        auto ldfrag = [&](int ks, int buf) {     // ks: k16 step within k64 tile
            const uint32_t kb = (uint32_t)ks * 32;
            #pragma unroll
            for (int i = 0; i < 4; i++) {
                const int rb = wm * 64 + i * 16;
                const uint32_t off = (uint32_t)((rb + a_row) * 128) + kb + a_kofb;
                ldmx4s(af[buf][i], abase + sw128(off));
            }
            #pragma unroll
            for (int jp = 0; jp < 4; jp++) {
                uint32_t bq[4];
                const int nb = wn * 64 + jp * 16;
                const uint32_t off = (uint32_t)((nb + b_row) * 128) + kb + b_kofb;
                ldmx4s(bq, bbase + sw128(off));
                bf[buf][jp * 2][0]     = bq[0];
                bf[buf][jp * 2][1]     = bq[1];
                bf[buf][jp * 2 + 1][0] = bq[2];
                bf[buf][jp * 2 + 1][1] = bq[3];
            }
        };

        ldfrag(0, 0);
        if (kt + 2 < nkt) issue(kt + 2);

        #pragma unroll
        for (int ks = 0; ks < 4; ++ks) {
            const int cur = ks & 1;
            if (ks < 3) ldfrag(ks + 1, cur ^ 1);
            #pragma unroll
            for (int i = 0; i < 4; i++)
                #pragma unroll
                for (int j = 0; j < 8; j++)
                    mma16(acc[i][j], af[cur][i], bf[cur][j]);
        }
    }

    // ---- epilogue ----
    if (TRIPLE && vt != nullptr && bz == vtz) {
        // Write result transposed (vt[b][n][row]) via smem staging; skip C store.
        __syncthreads();
        float* ts = smf;                 // [128][129] floats
        #pragma unroll
        for (int i = 0; i < 4; i++) {
            const int rl = wm * 64 + i * 16 + g;
            #pragma unroll
            for (int j = 0; j < 8; j++) {
                const int cl = wn * 64 + j * 8 + tig * 2;
                ts[rl * 129 + cl]           = acc[i][j][0];
                ts[rl * 129 + cl + 1]       = acc[i][j][1];
                ts[(rl + 8) * 129 + cl]     = acc[i][j][2];
                ts[(rl + 8) * 129 + cl + 1] = acc[i][j][3];
            }
        }
        __syncthreads();
        const int b     = bm >> 11;          // bm / 2048
        const int sbase = bm & 2047;
        __half* vtp = vt + (size_t)b * ((size_t)SEQ * DMODEL);
        #pragma unroll 4
        for (int i = 0; i < 32; i++) {
            const int c = wid * 32 + i;
            __half* dstrow = vtp + (size_t)(bn + c) * SEQ + sbase;
            #pragma unroll
            for (int ch = 0; ch < 4; ch++) {
                const int s = lane + ch * 32;
                dstrow[s] = __float2half_rn(ts[s * 129 + c]);
            }
        }
        return;
    }

    #pragma unroll
    for (int i = 0; i < 4; i++) {
        const int r0 = bm + wm * 64 + i * 16 + g;
        float ri0 = 1.f, ri1 = 1.f;
        if (!MASKED && rowinv) {
            ri0 = rowinv[(size_t)bz * M + r0];
            ri1 = rowinv[(size_t)bz * M + r0 + 8];
        }
        #pragma unroll
        for (int j = 0; j < 8; j++) {
            const int c0 = bn + wn * 64 + j * 8 + tig * 2;
            float v0 = acc[i][j][0], v1 = acc[i][j][1];
            float v2 = acc[i][j][2], v3 = acc[i][j][3];
            if (MASKED) {
                // scores path: p = exp(v*scale) (masked -> 0), fp16 store
                const size_t base = (size_t)bz * (size_t)M * N + (size_t)r0 * N;
                int m00, m01, m10, m11;
                if (mask_is_int32) {
                    const int* mi = (const int*)mask;
                    int2 ma = *(const int2*)&mi[base + c0];
                    int2 mb = *(const int2*)&mi[base + (size_t)8 * N + c0];
                    m00 = ma.x; m01 = ma.y; m10 = mb.x; m11 = mb.y;
                } else {
                    m00 = mask[base + c0];                   m01 = mask[base + c0 + 1];
                    m10 = mask[base + (size_t)8 * N + c0];   m11 = mask[base + (size_t)8 * N + c0 + 1];
                }
                v0 = m00 ? __expf(v0 * scale) : 0.f;
                v1 = m01 ? __expf(v1 * scale) : 0.f;
                v2 = m10 ? __expf(v2 * scale) : 0.f;
                v3 = m11 ? __expf(v3 * scale) : 0.f;
            } else if (rowinv) {
                v0 *= ri0; v1 *= ri0; v2 *= ri1; v3 *= ri1;
            }
            if (HALF_OUT) {
                *(__half2*)&C16[(size_t)r0 * N + c0]       = __floats2half2_rn(v0, v1);
                *(__half2*)&C16[(size_t)(r0 + 8) * N + c0] = __floats2half2_rn(v2, v3);
            } else {
                float2 w0 = {v0, v1}, w1 = {v2, v3};
                *(float2*)&C32[(size_t)r0 * N + c0]       = w0;
                *(float2*)&C32[(size_t)(r0 + 8) * N + c0] = w1;
            }
        }
    }
}

// ---------------- host ----------------

extern "C" void kernel_launch(void* const* d_in, const int* in_sizes, int n_in,
                              void* d_out, int out_size)
{
    const float*         x    = (const float*)d_in[0];
    const unsigned char* mask = (const unsigned char*)d_in[1];
    const float*         Wq   = (const float*)d_in[2];
    const float*         Wk   = (const float*)d_in[3];
    const float*         Wv   = (const float*)d_in[4];
    const float*         Wo   = (const float*)d_in[5];
    float*               out  = (float*)d_out;

    __half *X, *T, *P16, *VT, *WH;
    float *RS;
    cudaGetSymbolAddress((void**)&X,   g_X16);
    cudaGetSymbolAddress((void**)&T,   g_T16);
    cudaGetSymbolAddress((void**)&P16, g_P16);
    cudaGetSymbolAddress((void**)&VT,  g_VT16);
    cudaGetSymbolAddress((void**)&WH,  g_WH);
    cudaGetSymbolAddress((void**)&RS,  g_RS);

    const size_t pstride = (size_t)BATCH * SEQ * DMODEL;   // full activation plane (elems)
    const size_t bstride = (size_t)SEQ * DMODEL;           // per-batch plane
    const size_t wsz = (size_t)DMODEL * DMODEL;
    __half* q16   = WH;               // Wq fp16 (row-major)
    __half* k16   = WH + wsz;         // Wk fp16
    __half* v16   = WH + 2 * wsz;     // Wv fp16
    __half* WoT   = WH + 3 * wsz;     // Wo^T fp16
    __half* WqkT  = WH + 4 * wsz;     // (Wq Wk^T)^T = Wk Wq^T
    __half* WvoT  = WH + 5 * wsz;     // (Wv Wo)^T

    // --- pre-pass: fp16 conversions + Wo transpose ---
    {
        const int xe4 = (int)(pstride / 4);
        to_half<<<(xe4 + 255) / 256, 256>>>((const float4*)x, X, xe4);
        const int we4 = (int)(wsz / 4);
        to_half<<<(we4 + 255) / 256, 256>>>((const float4*)Wq, q16, we4);
        to_half<<<(we4 + 255) / 256, 256>>>((const float4*)Wk, k16, we4);
        to_half<<<(we4 + 255) / 256, 256>>>((const float4*)Wv, v16, we4);
        dim3 tb(32, 8);
        dim3 tg(DMODEL / 32, DMODEL / 32, 1);
        transpose_h<<<tg, tb>>>(Wo, WoT);
    }

    const int smemB = 3 * 32768 + 128;   // 3 stages + alignment slack
    cudaFuncSetAttribute(gemm_h<true,  true,  false>,
                         cudaFuncAttributeMaxDynamicSharedMemorySize, smemB);
    cudaFuncSetAttribute(gemm_h<false, true,  true>,
                         cudaFuncAttributeMaxDynamicSharedMemorySize, smemB);
    cudaFuncSetAttribute(gemm_h<false, false, false>,
                         cudaFuncAttributeMaxDynamicSharedMemorySize, smemB);

    const int MS = BATCH * SEQ;   // 8192
    dim3 blk(128);

    // Weight combos (one launch, 2 z-planes):
    //   z0: WqkT = Wk * Wq^T      z1: WvoT = WoT * Wv^T (i.e. (Wv*Wo)^T)
    dim3 gw(DMODEL / 128, DMODEL / 128, 2);
    gemm_h<true, true, false><<<gw, blk, smemB>>>(
        k16, WoT, q16, v16, WqkT, DMODEL, DMODEL, DMODEL, 0, 0, wsz,
        nullptr, 1.f, nullptr, nullptr, -1);

    // Activations (one launch, 2 z-planes, shared A=X):
    //   z0: T = x * WqkT^T (fp16)   z1: VO = x * WvoT^T -> written transposed to VT
    dim3 ga(DMODEL / 128, MS / 128, 2);
    gemm_h<true, true, false><<<ga, blk, smemB>>>(
        X, X, WqkT, WvoT, T, MS, DMODEL, DMODEL, 0, 0, 0,
        nullptr, 1.f, nullptr, VT, 1);

    // P = exp(T x^T / 32) masked->0, fp16 out (per batch)
    dim3 gs(SEQ / 128, SEQ / 128, BATCH);
    gemm_h<false, true, true><<<gs, blk, smemB>>>(
        T, nullptr, X, nullptr, P16, SEQ, SEQ, DMODEL,
        bstride, bstride, (size_t)SEQ * SEQ, mask, 0.03125f, nullptr, nullptr, -1);

    // 1/rowsum of P
    rowsum_inv_h<<<BATCH * SEQ, 256>>>(P16, RS);

    // out = rowinv ⊙ (P * VO)  (fp32 final output, per batch)
    dim3 gv(DMODEL / 128, SEQ / 128, BATCH);
    gemm_h<false, false, false><<<gv, blk, smemB>>>(
        P16, nullptr, VT, nullptr, out, SEQ, DMODEL, SEQ,
        (size_t)SEQ * SEQ, bstride, bstride, nullptr, 1.f, RS, nullptr, -1);
}